// round 16
// baseline (speedup 1.0000x reference)
#include <cuda_runtime.h>

#define NWORDS 100000
#define NQ 50
#define NS 64
#define NBLOCKS 782   // ceil(100000 / 128)

// Heads, 3-array half-split layout: for comp c in {0,1,2}, q:
//   row of 64 floats = [qt0 first-4][qt1 first-4]...[qt7 first-4]
//                      [qt0 second-4][qt1 second-4]...[qt7 second-4]
// -> both LDS.128 per comp at qt*16B offsets: conflict-free.
__device__ __align__(16) float g_hH3[3 * NQ * 64];
__device__ __align__(8)  float g_hr[NS];
__device__ double g_acc = 0.0;
__device__ unsigned int g_counter = 0u;

typedef unsigned long long u64;

__device__ __forceinline__ u64 bc2(float x) {
    u64 r; asm("mov.b64 %0, {%1, %1};" : "=l"(r) : "f"(x)); return r;
}
__device__ __forceinline__ u64 fma2(u64 a, u64 b, u64 c) {
    u64 d; asm("fma.rn.f32x2 %0, %1, %2, %3;" : "=l"(d) : "l"(a), "l"(b), "l"(c)); return d;
}
__device__ __forceinline__ u64 mul2(u64 a, u64 b) {
    u64 d; asm("mul.rn.f32x2 %0, %1, %2;" : "=l"(d) : "l"(a), "l"(b)); return d;
}
__device__ __forceinline__ void up2(u64 a, float& x, float& y) {
    asm("mov.b64 {%0, %1}, %2;" : "=f"(x), "=f"(y) : "l"(a));
}

__device__ __forceinline__ float sp20(float x) {
    float y = 20.0f * x;
    return fmaxf(y, 0.0f) + log1pf(expf(-fabsf(y)));
}

__global__ void setup_kernel(const float* __restrict__ hp, const float* __restrict__ hrp) {
    int tid = threadIdx.x;
    if (blockIdx.x == 0) {
        __shared__ float sv[NS];
        __shared__ float ssum;
        if (tid < NS) sv[tid] = sp20(hrp[tid]);
        __syncthreads();
        if (tid == 0) {
            float s = 0.0f;
            for (int i = 0; i < NS; i++) s += sv[i];
            ssum = fmaxf(s, 1e-12f);
        }
        __syncthreads();
        if (tid < NS) g_hr[tid] = (sv[tid] / ssum + 0.001f / (float)NS) / 1.001f;
    }
    int idx = blockIdx.x * blockDim.x + tid;
    if (idx < NS * NQ) {
        int q = idx >> 6;
        int s = idx & 63;
        const float* p = hp + ((size_t)s * NQ + q) * 3;
        float v0 = sp20(p[0]);
        float v1 = sp20(p[1]);
        float v2 = sp20(p[2]);
        float sm = fmaxf((v0 + v1) + v2, 1e-12f);
        int qt = s >> 3, k = s & 7;
        int off = (k >> 2) * 32 + qt * 4 + (k & 3);   // half-split position
        g_hH3[(0 * NQ + q) * 64 + off] = v0 / sm;
        g_hH3[(1 * NQ + q) * 64 + off] = v1 / sm;
        g_hH3[(2 * NQ + q) * 64 + off] = v2 / sm;
    }
}

// Thread = (n-quad, s-octant). 256 threads -> 32 n-quads (128 n) x 8 s-octants.
// smem: heads 9600 f (38.4KB) + 2 x tile buffer (15 rows x pitch 164, 5-q chunk)
#define SH_HEADS 9600
#define SH_TROW  164
#define SH_TBUF  (15 * SH_TROW + 32)          // 2492 floats
#define SMEM_FLOATS (SH_HEADS + 2 * SH_TBUF)  // 14584 floats = 58.3KB

// per-row 16B swizzle keeps staging STS conflicts low:
#define TROW_OFF(r) ((r) * SH_TROW + 4 * (((r) >> 1) & 7))

#define CP_ASYNC4(dst_u32, src_ptr) \
    asm volatile("cp.async.ca.shared.global [%0], [%1], 4;" :: "r"(dst_u32), "l"(src_ptr))
#define CP_COMMIT()  asm volatile("cp.async.commit_group;" ::: "memory")
#define CP_WAIT1()   asm volatile("cp.async.wait_group 1;" ::: "memory")
#define CP_WAIT0()   asm volatile("cp.async.wait_group 0;" ::: "memory")

__global__ __launch_bounds__(256, 3)
void cov_kernel(const float* __restrict__ tpl, const float* __restrict__ coeff,
                float* __restrict__ out) {
    extern __shared__ __align__(16) float smem[];
    float* sH = smem;

    const int tid   = threadIdx.x;
    const int qt    = tid & 7;          // s-octant 0..7 (8 heads each)
    const int nq    = tid >> 3;         // n-quad 0..31
    const int nBase = blockIdx.x * 128;

    const unsigned int smem_base =
        (unsigned int)__cvta_generic_to_shared(smem);
    const unsigned int tbuf_base[2] = {
        smem_base + SH_HEADS * 4,
        smem_base + (SH_HEADS + SH_TBUF) * 4
    };

    // stage heads table (38.4 KB) once per block (plain copy; covered by 1st sync)
    {
        const float4* src = (const float4*)g_hH3;
        float4* dst = (float4*)sH;
        for (int i = tid; i < SH_HEADS / 4; i += 256) dst[i] = src[i];
    }

    // stage chunk 0 (qc = 0) via cp.async: 128 rows x 15 floats (5 q x 3 p)
    {
        for (int i = tid; i < 128 * 15; i += 256) {
            int nl = i / 15;
            int r  = i - nl * 15;
            int n  = nBase + nl;
            n = (n < NWORDS) ? n : (NWORDS - 1);
            const float* src = tpl + (size_t)n * (NQ * 3) + r;
            CP_ASYNC4(tbuf_base[0] + 4u * (unsigned)(TROW_OFF(r) + nl), src);
        }
        CP_COMMIT();
    }

    const u64 ONE = 0x3f8000003f800000ULL;
    u64 prod[4][4];
#pragma unroll
    for (int p = 0; p < 4; p++)
#pragma unroll
        for (int n = 0; n < 4; n++) prod[p][n] = ONE;

#pragma unroll 1
    for (int c = 0; c < 10; c++) {
        // stage next chunk into the other buffer
        if (c < 9) {
            unsigned int dstb = tbuf_base[(c + 1) & 1];
            int qoff = (c + 1) * 15;
            for (int i = tid; i < 128 * 15; i += 256) {
                int nl = i / 15;
                int r  = i - nl * 15;
                int n  = nBase + nl;
                n = (n < NWORDS) ? n : (NWORDS - 1);
                const float* src = tpl + (size_t)n * (NQ * 3) + qoff + r;
                CP_ASYNC4(dstb + 4u * (unsigned)(TROW_OFF(r) + nl), src);
            }
            CP_COMMIT();
            CP_WAIT1();    // chunk c's loads complete (issued one phase ago)
        } else {
            CP_WAIT0();
        }
        __syncthreads();

        const float* sT = smem + SH_HEADS + (c & 1) * SH_TBUF;
        const int qbase = c * 5;
#pragma unroll 1
        for (int qq = 0; qq < 5; qq++) {
            int q = qbase + qq;
            // heads: 2 conflict-free LDS.128 per component
            const float* h0r = sH + (0 * NQ + q) * 64;
            const float* h1r = sH + (1 * NQ + q) * 64;
            const float* h2r = sH + (2 * NQ + q) * 64;
            ulonglong2 A0 = *(const ulonglong2*)(h0r + qt * 4);
            ulonglong2 A1 = *(const ulonglong2*)(h0r + 32 + qt * 4);
            ulonglong2 B0 = *(const ulonglong2*)(h1r + qt * 4);
            ulonglong2 B1 = *(const ulonglong2*)(h1r + 32 + qt * 4);
            ulonglong2 C0 = *(const ulonglong2*)(h2r + qt * 4);
            ulonglong2 C1 = *(const ulonglong2*)(h2r + 32 + qt * 4);
            // A0 = h0 pairs (s0,s1),(s2,s3); A1 = (s4,s5),(s6,s7), s = qt*8+k

            int r0i = qq * 3;
            float4 r0 = *(const float4*)(sT + TROW_OFF(r0i)     + nq * 4);
            float4 r1 = *(const float4*)(sT + TROW_OFF(r0i + 1) + nq * 4);
            float4 r2 = *(const float4*)(sT + TROW_OFF(r0i + 2) + nq * 4);
            u64 T0[4], T1[4], T2[4];
            T0[0] = bc2(r0.x); T0[1] = bc2(r0.y); T0[2] = bc2(r0.z); T0[3] = bc2(r0.w);
            T1[0] = bc2(r1.x); T1[1] = bc2(r1.y); T1[2] = bc2(r1.z); T1[3] = bc2(r1.w);
            T2[0] = bc2(r2.x); T2[1] = bc2(r2.y); T2[2] = bc2(r2.z); T2[3] = bc2(r2.w);

#pragma unroll
            for (int n = 0; n < 4; n++) {
                u64 a = mul2(C0.x, T2[n]);
                a = fma2(B0.x, T1[n], a);
                a = fma2(A0.x, T0[n], a);
                prod[0][n] = mul2(prod[0][n], a);
                u64 b = mul2(C0.y, T2[n]);
                b = fma2(B0.y, T1[n], b);
                b = fma2(A0.y, T0[n], b);
                prod[1][n] = mul2(prod[1][n], b);
                u64 cc = mul2(C1.x, T2[n]);
                cc = fma2(B1.x, T1[n], cc);
                cc = fma2(A1.x, T0[n], cc);
                prod[2][n] = mul2(prod[2][n], cc);
                u64 d = mul2(C1.y, T2[n]);
                d = fma2(B1.y, T1[n], d);
                d = fma2(A1.y, T0[n], d);
                prod[3][n] = mul2(prod[3][n], d);
            }
        }
        if (c < 9) __syncthreads();   // all warps done with buf[c&1] before overwrite
    }

    // ratio-weighted partial covs for this thread's 4 n over its 8 heads
    float cov[4] = {0.f, 0.f, 0.f, 0.f};
#pragma unroll
    for (int p = 0; p < 4; p++) {
        float2 w = *(const float2*)(g_hr + (size_t)qt * 8 + p * 2);
#pragma unroll
        for (int n = 0; n < 4; n++) {
            float lo, hi;
            up2(prod[p][n], lo, hi);
            cov[n] = fmaf(w.x, lo, cov[n]);
            cov[n] = fmaf(w.y, hi, cov[n]);
        }
    }
    // combine the 8 s-octants (8 consecutive lanes share an n-quad)
#pragma unroll
    for (int o = 1; o <= 4; o <<= 1)
#pragma unroll
        for (int n = 0; n < 4; n++)
            cov[n] += __shfl_xor_sync(0xffffffffu, cov[n], o);

    double term = 0.0;
    if (qt == 0) {
        int n0 = nBase + nq * 4;
#pragma unroll
        for (int k = 0; k < 4; k++) {
            if (n0 + k < NWORDS) {
                float c = coeff[n0 + k];
                term += ((double)c * (double)c) / (double)cov[k];
            }
        }
    }
#pragma unroll
    for (int o = 16; o > 0; o >>= 1)
        term += __shfl_down_sync(0xffffffffu, term, o);

    __shared__ double sAcc[8];
    if ((tid & 31) == 0) sAcc[tid >> 5] = term;
    __syncthreads();
    if (tid == 0) {
        double t = 0.0;
#pragma unroll
        for (int w = 0; w < 8; w++) t += sAcc[w];
        atomicAdd(&g_acc, t);
        __threadfence();
        unsigned int done = atomicAdd(&g_counter, 1u);
        if (done == NBLOCKS - 1) {
            out[0] = (float)g_acc;
            g_acc = 0.0;
            g_counter = 0u;
        }
    }
}

extern "C" void kernel_launch(void* const* d_in, const int* in_sizes, int n_in,
                              void* d_out, int out_size) {
    const float* tpl = (const float*)d_in[0];   // batch_pauli_tensor [N,Q,P] f32
    const float* cf  = (const float*)d_in[1];   // batch_coeff [N]
    const float* hp  = (const float*)d_in[2];   // heads_param [S,Q,P]
    const float* hrp = (const float*)d_in[3];   // head_ratios_param [S]

    cudaFuncSetAttribute(cov_kernel, cudaFuncAttributeMaxDynamicSharedMemorySize,
                         SMEM_FLOATS * sizeof(float));

    setup_kernel<<<13, 256>>>(hp, hrp);
    cov_kernel<<<NBLOCKS, 256, SMEM_FLOATS * sizeof(float)>>>(tpl, cf, (float*)d_out);
}